// round 1
// baseline (speedup 1.0000x reference)
#include <cuda_runtime.h>
#include <cuda_bf16.h>

// Problem constants
#define SEQ   1024
#define DIM   64
#define BH    64          // B*H = 8*8 heads
#define NB    131072      // histogram bins per head over (-1,1)
#define NTOT  1048576     // S*S elements ranked per head
#define INV_N (1.0f/1048576.0f)

// ---------------- scratch (static device globals; no runtime alloc) ------------
__device__ float    g_qn[(size_t)BH*SEQ*DIM];        // normalized Q  (16MB)
__device__ float    g_kn[(size_t)BH*SEQ*DIM];        // normalized K  (16MB)
__device__ float    g_scores[(size_t)BH*SEQ*SEQ];    // scores, then weights in place (256MB)
__device__ unsigned g_hist[(size_t)BH*NB];           // hist -> packed (SA<<12|cnt) (32MB)
__device__ unsigned g_part[BH*128];                  // per-chunk partials
__device__ float    g_rowsum[BH*SEQ];                // weight row sums

// ---------------- helpers ----------------
__device__ __forceinline__ int binof(float x) {
    int b = (int)((x + 1.0f) * 65536.0f);   // NB/2 per unit
    b = b < 0 ? 0 : b;
    b = b > (NB-1) ? (NB-1) : b;
    return b;
}

// ---------------- K-1: clear histogram ----------------
__global__ __launch_bounds__(256) void k_clear() {
    size_t i = (size_t)blockIdx.x * blockDim.x + threadIdx.x;   // 8192*256 = 2,097,152 uint4
    ((uint4*)g_hist)[i] = make_uint4(0u,0u,0u,0u);
}

// ---------------- K0: cosine-normalize Q and K (warp per row) ----------------
__global__ __launch_bounds__(256) void k_normalize(const float* __restrict__ q,
                                                   const float* __restrict__ k) {
    int w    = blockIdx.x * 8 + (threadIdx.x >> 5);   // global warp id, 0..131071
    int lane = threadIdx.x & 31;
    int r    = w & 65535;
    const float* src;
    float* dst;
    if (w < 65536) { src = q + (size_t)r*64; dst = g_qn + (size_t)r*64; }
    else           { src = k + (size_t)r*64; dst = g_kn + (size_t)r*64; }
    float x0 = src[lane], x1 = src[lane+32];
    float ss = x0*x0 + x1*x1;
    #pragma unroll
    for (int o = 16; o; o >>= 1) ss += __shfl_xor_sync(0xffffffffu, ss, o);
    float inv = 1.0f / (sqrtf(ss) + 1e-5f);
    dst[lane]    = x0*inv;
    dst[lane+32] = x1*inv;
}

// ---------------- K1: score GEMM (64x64 tile, K=64) + scores + histogram ------
__global__ __launch_bounds__(256) void k_score() {
    __shared__ float Qs[64][64];   // [d][q]
    __shared__ float Ks[64][64];   // [d][k]
    int t    = threadIdx.x;
    int head = blockIdx.z, qt = blockIdx.y, kt = blockIdx.x;
    int qr   = t & 63, half = t >> 6;

    const float* Qg = g_qn + ((size_t)head*SEQ + qt*64 + qr) * 64;
    const float* Kg = g_kn + ((size_t)head*SEQ + kt*64 + qr) * 64;
    #pragma unroll
    for (int j = 0; j < 4; j++) {
        int fi = half + 4*j;
        float4 a = ((const float4*)Qg)[fi];
        Qs[4*fi+0][qr]=a.x; Qs[4*fi+1][qr]=a.y; Qs[4*fi+2][qr]=a.z; Qs[4*fi+3][qr]=a.w;
        float4 b = ((const float4*)Kg)[fi];
        Ks[4*fi+0][qr]=b.x; Ks[4*fi+1][qr]=b.y; Ks[4*fi+2][qr]=b.z; Ks[4*fi+3][qr]=b.w;
    }
    __syncthreads();

    int tx = t & 15, ty = t >> 4;
    float c[4][4] = {};
    #pragma unroll 16
    for (int kk = 0; kk < 64; kk++) {
        float4 a = *(const float4*)&Qs[kk][4*ty];
        float4 b = *(const float4*)&Ks[kk][4*tx];
        c[0][0]+=a.x*b.x; c[0][1]+=a.x*b.y; c[0][2]+=a.x*b.z; c[0][3]+=a.x*b.w;
        c[1][0]+=a.y*b.x; c[1][1]+=a.y*b.y; c[1][2]+=a.y*b.z; c[1][3]+=a.y*b.w;
        c[2][0]+=a.z*b.x; c[2][1]+=a.z*b.y; c[2][2]+=a.z*b.z; c[2][3]+=a.z*b.w;
        c[3][0]+=a.w*b.x; c[3][1]+=a.w*b.y; c[3][2]+=a.w*b.z; c[3][3]+=a.w*b.w;
    }

    unsigned* hist = g_hist + (size_t)head * NB;
    #pragma unroll
    for (int i = 0; i < 4; i++) {
        int q = qt*64 + 4*ty + i;
        float4 s = make_float4(c[i][0], c[i][1], c[i][2], c[i][3]);
        atomicAdd(&hist[binof(s.x)], 1u);
        atomicAdd(&hist[binof(s.y)], 1u);
        atomicAdd(&hist[binof(s.z)], 1u);
        atomicAdd(&hist[binof(s.w)], 1u);
        *(float4*)(g_scores + ((size_t)head*SEQ + q) * SEQ + kt*64 + 4*tx) = s;
    }
}

// ---------------- K2a: per-1024-bin chunk sums ----------------
__global__ __launch_bounds__(256) void k_hpart() {
    int head = blockIdx.y, chunk = blockIdx.x, t = threadIdx.x;
    const unsigned* h = g_hist + (size_t)head*NB + chunk*1024;
    unsigned s = h[t] + h[t+256] + h[t+512] + h[t+768];
    __shared__ unsigned sm[8];
    #pragma unroll
    for (int o = 16; o; o >>= 1) s += __shfl_xor_sync(0xffffffffu, s, o);
    if ((t & 31) == 0) sm[t >> 5] = s;
    __syncthreads();
    if (t < 8) {
        unsigned v = sm[t];
        #pragma unroll
        for (int o = 4; o; o >>= 1) v += __shfl_xor_sync(0xffu, v, o);
        if (t == 0) g_part[head*128 + chunk] = v;
    }
}

// ---------------- K2b: suffix-exclusive scan of the 128 chunk sums per head ---
__global__ __launch_bounds__(128) void k_hscan() {
    int head = blockIdx.x, t = threadIdx.x;
    __shared__ unsigned s[128];
    unsigned v = g_part[head*128 + t];
    s[t] = v; __syncthreads();
    for (int off = 1; off < 128; off <<= 1) {
        unsigned add = (t + off < 128) ? s[t + off] : 0u;
        __syncthreads();
        s[t] += add;
        __syncthreads();
    }
    g_part[head*128 + t] = s[t] - v;    // elements in strictly-higher chunks
}

// ---------------- K2c: in-chunk suffix scan, pack (SA<<12|cnt) in place -------
__global__ __launch_bounds__(256) void k_hfinal() {
    int head = blockIdx.y, chunk = blockIdx.x, t = threadIdx.x;
    unsigned* h = g_hist + (size_t)head*NB + chunk*1024;
    uint4 v = ((uint4*)h)[t];
    unsigned tot = v.x + v.y + v.z + v.w;
    __shared__ unsigned s[256];
    s[t] = tot; __syncthreads();
    for (int off = 1; off < 256; off <<= 1) {
        unsigned add = (t + off < 256) ? s[t + off] : 0u;
        __syncthreads();
        s[t] += add;
        __syncthreads();
    }
    unsigned above = s[t] - tot + g_part[head*128 + chunk];
    unsigned SA3 = above;
    unsigned SA2 = SA3 + v.w;
    unsigned SA1 = SA2 + v.z;
    unsigned SA0 = SA1 + v.y;
    uint4 o;
    o.x = (SA0 << 12) | min(v.x, 4095u);
    o.y = (SA1 << 12) | min(v.y, 4095u);
    o.z = (SA2 << 12) | min(v.z, 4095u);
    o.w = (SA3 << 12) | min(v.w, 4095u);
    ((uint4*)h)[t] = o;
}

// ---------------- K3: scores -> weights (in place) + row sums ----------------
__device__ __forceinline__ float wcalc(float x, const unsigned* __restrict__ lut) {
    int bin = binof(x);
    unsigned p = __ldg(&lut[bin]);
    float SA  = (float)(p >> 12);
    float cnt = (float)(p & 4095u);
    float rank = SA + 0.5f * (cnt - 1.0f);     // midpoint rank of this bin
    return -__logf((rank + 1.0f) * INV_N);
}

__global__ __launch_bounds__(256) void k_weight() {
    int row  = blockIdx.x;            // bh*1024 + q
    int head = row >> 10;
    int t    = threadIdx.x;
    float* sp = g_scores + (size_t)row * SEQ;
    const unsigned* lut = g_hist + (size_t)head * NB;

    float4 s = ((float4*)sp)[t];
    float4 w;
    w.x = wcalc(s.x, lut);
    w.y = wcalc(s.y, lut);
    w.z = wcalc(s.z, lut);
    w.w = wcalc(s.w, lut);
    ((float4*)sp)[t] = w;

    float sum = w.x + w.y + w.z + w.w;
    __shared__ float sm[8];
    #pragma unroll
    for (int o = 16; o; o >>= 1) sum += __shfl_xor_sync(0xffffffffu, sum, o);
    if ((t & 31) == 0) sm[t >> 5] = sum;
    __syncthreads();
    if (t < 8) {
        float v = sm[t];
        #pragma unroll
        for (int o = 4; o; o >>= 1) v += __shfl_xor_sync(0xffu, v, o);
        if (t == 0) g_rowsum[row] = v;
    }
}

// ---------------- K4: output GEMM  O = (W @ V) / rowsum ----------------
__global__ __launch_bounds__(256) void k_out(const float* __restrict__ V,
                                             float* __restrict__ O) {
    __shared__ float Ws[64][64];   // [k][q]
    __shared__ float Vs[64][64];   // [k][d]
    int t = threadIdx.x, head = blockIdx.y, qt = blockIdx.x;
    int qr = t & 63, half = t >> 6;
    int tx = t & 15, ty = t >> 4;
    float c[4][4] = {};

    const float* Wg = g_scores + ((size_t)head*SEQ + qt*64 + qr) * SEQ;
    const float* Vg = V + (size_t)head * (SEQ*DIM);

    for (int kc = 0; kc < 16; kc++) {
        #pragma unroll
        for (int j = 0; j < 4; j++) {
            int fi = half + 4*j;
            float4 a = ((const float4*)Wg)[kc*16 + fi];
            Ws[4*fi+0][qr]=a.x; Ws[4*fi+1][qr]=a.y; Ws[4*fi+2][qr]=a.z; Ws[4*fi+3][qr]=a.w;
        }
        #pragma unroll
        for (int m = 0; m < 4; m++) {
            int rowk = t >> 2;
            int col4 = (t & 3) + 4*m;
            float4 b = ((const float4*)(Vg + (size_t)(kc*64 + rowk)*64))[col4];
            *(float4*)&Vs[rowk][col4*4] = b;
        }
        __syncthreads();
        #pragma unroll 16
        for (int kk = 0; kk < 64; kk++) {
            float4 a = *(const float4*)&Ws[kk][4*ty];
            float4 b = *(const float4*)&Vs[kk][4*tx];
            c[0][0]+=a.x*b.x; c[0][1]+=a.x*b.y; c[0][2]+=a.x*b.z; c[0][3]+=a.x*b.w;
            c[1][0]+=a.y*b.x; c[1][1]+=a.y*b.y; c[1][2]+=a.y*b.z; c[1][3]+=a.y*b.w;
            c[2][0]+=a.z*b.x; c[2][1]+=a.z*b.y; c[2][2]+=a.z*b.z; c[2][3]+=a.z*b.w;
            c[3][0]+=a.w*b.x; c[3][1]+=a.w*b.y; c[3][2]+=a.w*b.z; c[3][3]+=a.w*b.w;
        }
        __syncthreads();
    }

    #pragma unroll
    for (int i = 0; i < 4; i++) {
        int q = qt*64 + 4*ty + i;
        float inv = 1.0f / g_rowsum[head*SEQ + q];
        float4 o = make_float4(c[i][0]*inv, c[i][1]*inv, c[i][2]*inv, c[i][3]*inv);
        *(float4*)(O + ((size_t)head*SEQ + q) * 64 + 4*tx) = o;
    }
}

// ---------------- launch ----------------
extern "C" void kernel_launch(void* const* d_in, const int* in_sizes, int n_in,
                              void* d_out, int out_size) {
    const float* q = (const float*)d_in[0];
    const float* k = (const float*)d_in[1];
    const float* v = (const float*)d_in[2];
    float* o = (float*)d_out;

    k_clear    <<<8192, 256>>>();
    k_normalize<<<16384, 256>>>(q, k);
    k_score    <<<dim3(16,16,64), 256>>>();
    k_hpart    <<<dim3(128,64), 256>>>();
    k_hscan    <<<64, 128>>>();
    k_hfinal   <<<dim3(128,64), 256>>>();
    k_weight   <<<65536, 256>>>();
    k_out      <<<dim3(16,64), 256>>>(v, o);
}

// round 3
// speedup vs baseline: 1.3607x; 1.3607x over previous
#include <cuda_runtime.h>
#include <cuda_bf16.h>

#define SEQ   1024
#define DIM   64
#define BH    64
#define NB    131072
#define INV_N (1.0f/1048576.0f)
#define STRD  72          // smem row stride in bf16 (144B) -> conflict-free ldmatrix

// ---------------- scratch ----------------
__device__ __nv_bfloat16 g_qhi[(size_t)BH*SEQ*DIM];
__device__ __nv_bfloat16 g_qlo[(size_t)BH*SEQ*DIM];
__device__ __nv_bfloat16 g_khi[(size_t)BH*SEQ*DIM];
__device__ __nv_bfloat16 g_klo[(size_t)BH*SEQ*DIM];
__device__ __nv_bfloat16 g_vthi[(size_t)BH*DIM*SEQ];   // V^T [head][d][k]
__device__ __nv_bfloat16 g_vtlo[(size_t)BH*DIM*SEQ];
__device__ unsigned      g_bins[(size_t)BH*SEQ*SEQ];   // bin index per score (256MB)
__device__ __nv_bfloat16 g_whi[(size_t)BH*SEQ*SEQ];    // weight hi (128MB)
__device__ __nv_bfloat16 g_wlo[(size_t)BH*SEQ*SEQ];    // weight lo (128MB)
__device__ unsigned      g_hist[(size_t)BH*NB];        // counts -> packed (SA<<12|cnt)
__device__ unsigned      g_part[BH*128];
__device__ float         g_rowsum[BH*SEQ];

// ---------------- helpers ----------------
__device__ __forceinline__ int binof(float x) {
    int b = (int)((x + 1.0f) * 65536.0f);
    b = b < 0 ? 0 : b;
    b = b > (NB-1) ? (NB-1) : b;
    return b;
}
__device__ __forceinline__ unsigned s2u(const void* p) {
    unsigned a;
    asm("{ .reg .u64 t; cvta.to.shared.u64 t, %1; cvt.u32.u64 %0, t; }" : "=r"(a) : "l"(p));
    return a;
}
__device__ __forceinline__ void ldm4(unsigned r[4], unsigned a) {
    asm volatile("ldmatrix.sync.aligned.m8n8.x4.shared.b16 {%0,%1,%2,%3}, [%4];"
        : "=r"(r[0]), "=r"(r[1]), "=r"(r[2]), "=r"(r[3]) : "r"(a));
}
__device__ __forceinline__ void mma16816(float c[4], const unsigned a[4],
                                         unsigned b0, unsigned b1) {
    asm volatile("mma.sync.aligned.m16n8k16.row.col.f32.bf16.bf16.f32 "
        "{%0,%1,%2,%3}, {%4,%5,%6,%7}, {%8,%9}, {%0,%1,%2,%3};"
        : "+f"(c[0]), "+f"(c[1]), "+f"(c[2]), "+f"(c[3])
        : "r"(a[0]), "r"(a[1]), "r"(a[2]), "r"(a[3]), "r"(b0), "r"(b1));
}
__device__ __forceinline__ void split2(float x, __nv_bfloat16& h, __nv_bfloat16& l) {
    h = __float2bfloat16_rn(x);
    l = __float2bfloat16_rn(x - __bfloat162float(h));
}

// ---------------- clear histogram ----------------
__global__ __launch_bounds__(256) void k_clear() {
    size_t i = (size_t)blockIdx.x * blockDim.x + threadIdx.x;
    ((uint4*)g_hist)[i] = make_uint4(0u,0u,0u,0u);
}

// ---------------- normalize + split Q,K to bf16 hi/lo ----------------
__global__ __launch_bounds__(256) void k_qksplit(const float* __restrict__ q,
                                                 const float* __restrict__ k) {
    int w    = blockIdx.x * 8 + (threadIdx.x >> 5);
    int lane = threadIdx.x & 31;
    int r    = w & 65535;
    const float* src = (w < 65536) ? q + (size_t)r*64 : k + (size_t)r*64;
    __nv_bfloat16* dh = (w < 65536) ? g_qhi : g_khi;
    __nv_bfloat16* dl = (w < 65536) ? g_qlo : g_klo;
    float x0 = src[lane], x1 = src[lane+32];
    float ss = x0*x0 + x1*x1;
    #pragma unroll
    for (int o = 16; o; o >>= 1) ss += __shfl_xor_sync(0xffffffffu, ss, o);
    float inv = 1.0f / (sqrtf(ss) + 1e-5f);
    x0 *= inv; x1 *= inv;
    __nv_bfloat16 h, l;
    split2(x0, h, l); dh[(size_t)r*64 + lane]      = h; dl[(size_t)r*64 + lane]      = l;
    split2(x1, h, l); dh[(size_t)r*64 + lane + 32] = h; dl[(size_t)r*64 + lane + 32] = l;
}

// ---------------- transpose + split V ----------------
__global__ __launch_bounds__(256) void k_vsplit(const float* __restrict__ V) {
    __shared__ float t[64][65];
    int head = blockIdx.y, kc = blockIdx.x, tid = threadIdx.x;
    const float* src = V + ((size_t)head*SEQ + kc*64) * 64;
    #pragma unroll
    for (int i = 0; i < 4; i++) {
        int idx = tid + i*256;
        int r = idx >> 4, c4 = idx & 15;
        float4 v = ((const float4*)(src + (size_t)r*64))[c4];
        t[r][c4*4+0]=v.x; t[r][c4*4+1]=v.y; t[r][c4*4+2]=v.z; t[r][c4*4+3]=v.w;
    }
    __syncthreads();
    #pragma unroll
    for (int i = 0; i < 8; i++) {
        int idx = tid + i*256;
        int d = idx >> 5, rp = idx & 31;
        float x0 = t[rp*2][d], x1 = t[rp*2+1][d];
        __nv_bfloat16 h0,l0,h1,l1;
        split2(x0,h0,l0); split2(x1,h1,l1);
        size_t o = ((size_t)head*64 + d)*SEQ + kc*64 + rp*2;
        *(__nv_bfloat162*)(g_vthi + o) = __halves2bfloat162(h0, h1);
        *(__nv_bfloat162*)(g_vtlo + o) = __halves2bfloat162(l0, l1);
    }
}

// ---------------- score GEMM (HMMA, split bf16) -> bins + histogram ----------
__global__ __launch_bounds__(256) void k_score() {
    extern __shared__ __nv_bfloat16 sm[];
    const int TQH = 0, TQL = 128*STRD, TKH = 2*128*STRD, TKL = 3*128*STRD;
    int tid = threadIdx.x, wid = tid >> 5, lane = tid & 31;
    int kt = blockIdx.x, qt = blockIdx.y, head = blockIdx.z;

    size_t bq = ((size_t)head*SEQ + qt*128) * 64;
    size_t bk = ((size_t)head*SEQ + kt*128) * 64;
    const uint4* srcs[4] = { (const uint4*)(g_qhi+bq), (const uint4*)(g_qlo+bq),
                             (const uint4*)(g_khi+bk), (const uint4*)(g_klo+bk) };
    const int bases[4] = { TQH, TQL, TKH, TKL };
    #pragma unroll
    for (int a = 0; a < 4; a++)
        #pragma unroll
        for (int j = 0; j < 4; j++) {
            int idx = tid + j*256;            // 1024 chunks of 16B
            int r = idx >> 3, c = idx & 7;
            uint4 v = srcs[a][idx];
            *(uint4*)&sm[bases[a] + r*STRD + c*8] = v;
        }
    __syncthreads();

    unsigned sb = s2u(sm);
    // A fragment addresses (row-major 16x16): lane -> row (l&15), khalf (l>>4)
    unsigned arow = wid*16 + (lane & 15);
    unsigned acol = (lane >> 4) * 8;
    unsigned aH = sb + (TQH + arow*STRD + acol) * 2;
    unsigned aL = sb + (TQL + arow*STRD + acol) * 2;
    unsigned ah[4][4], al[4][4];
    #pragma unroll
    for (int ks = 0; ks < 4; ks++) { ldm4(ah[ks], aH + ks*32); ldm4(al[ks], aL + ks*32); }

    // B fragment addresses (col-major n16k16 via x4): row = (l&7)+((l>>4)<<3), khalf=(l>>3)&1
    unsigned brow = (lane & 7) + ((lane >> 4) << 3);
    unsigned bcol = ((lane >> 3) & 1) * 8;
    unsigned bH = sb + (TKH + brow*STRD + bcol) * 2;
    unsigned bL = sb + (TKL + brow*STRD + bcol) * 2;

    float acc[16][4];
    #pragma unroll
    for (int i = 0; i < 16; i++) { acc[i][0]=0; acc[i][1]=0; acc[i][2]=0; acc[i][3]=0; }

    #pragma unroll
    for (int np = 0; np < 8; np++) {
        #pragma unroll
        for (int ks = 0; ks < 4; ks++) {
            unsigned bh[4], bl[4];
            ldm4(bh, bH + np*16*STRD*2 + ks*32);
            ldm4(bl, bL + np*16*STRD*2 + ks*32);
            mma16816(acc[2*np],   ah[ks], bh[0], bh[1]);
            mma16816(acc[2*np+1], ah[ks], bh[2], bh[3]);
            mma16816(acc[2*np],   ah[ks], bl[0], bl[1]);
            mma16816(acc[2*np+1], ah[ks], bl[2], bl[3]);
            mma16816(acc[2*np],   al[ks], bh[0], bh[1]);
            mma16816(acc[2*np+1], al[ks], bh[2], bh[3]);
        }
    }

    unsigned* hist = g_hist + (size_t)head * NB;
    int r0 = wid*16 + (lane >> 2);
    int cb = (lane & 3) * 2;
    unsigned* bp0 = g_bins + ((size_t)head*SEQ + qt*128 + r0) * SEQ + kt*128;
    unsigned* bp1 = bp0 + 8*SEQ;
    #pragma unroll
    for (int nt = 0; nt < 16; nt++) {
        int c = nt*8 + cb;
        unsigned b0 = binof(acc[nt][0]), b1 = binof(acc[nt][1]);
        unsigned b2 = binof(acc[nt][2]), b3 = binof(acc[nt][3]);
        atomicAdd(&hist[b0], 1u); atomicAdd(&hist[b1], 1u);
        atomicAdd(&hist[b2], 1u); atomicAdd(&hist[b3], 1u);
        *(uint2*)&bp0[c] = make_uint2(b0, b1);
        *(uint2*)&bp1[c] = make_uint2(b2, b3);
    }
}

// ---------------- histogram suffix scan ----------------
__global__ __launch_bounds__(256) void k_hpart() {
    int head = blockIdx.y, chunk = blockIdx.x, t = threadIdx.x;
    const unsigned* h = g_hist + (size_t)head*NB + chunk*1024;
    unsigned s = h[t] + h[t+256] + h[t+512] + h[t+768];
    __shared__ unsigned sm[8];
    #pragma unroll
    for (int o = 16; o; o >>= 1) s += __shfl_xor_sync(0xffffffffu, s, o);
    if ((t & 31) == 0) sm[t >> 5] = s;
    __syncthreads();
    if (t < 8) {
        unsigned v = sm[t];
        #pragma unroll
        for (int o = 4; o; o >>= 1) v += __shfl_xor_sync(0xffu, v, o);
        if (t == 0) g_part[head*128 + chunk] = v;
    }
}
__global__ __launch_bounds__(128) void k_hscan() {
    int head = blockIdx.x, t = threadIdx.x;
    __shared__ unsigned s[128];
    unsigned v = g_part[head*128 + t];
    s[t] = v; __syncthreads();
    for (int off = 1; off < 128; off <<= 1) {
        unsigned add = (t + off < 128) ? s[t + off] : 0u;
        __syncthreads();
        s[t] += add;
        __syncthreads();
    }
    g_part[head*128 + t] = s[t] - v;
}
__global__ __launch_bounds__(256) void k_hfinal() {
    int head = blockIdx.y, chunk = blockIdx.x, t = threadIdx.x;
    unsigned* h = g_hist + (size_t)head*NB + chunk*1024;
    uint4 v = ((uint4*)h)[t];
    unsigned tot = v.x + v.y + v.z + v.w;
    __shared__ unsigned s[256];
    s[t] = tot; __syncthreads();
    for (int off = 1; off < 256; off <<= 1) {
        unsigned add = (t + off < 256) ? s[t + off] : 0u;
        __syncthreads();
        s[t] += add;
        __syncthreads();
    }
    unsigned above = s[t] - tot + g_part[head*128 + chunk];
    unsigned SA3 = above;
    unsigned SA2 = SA3 + v.w;
    unsigned SA1 = SA2 + v.z;
    unsigned SA0 = SA1 + v.y;
    uint4 o;
    o.x = (SA0 << 12) | min(v.x, 4095u);
    o.y = (SA1 << 12) | min(v.y, 4095u);
    o.z = (SA2 << 12) | min(v.z, 4095u);
    o.w = (SA3 << 12) | min(v.w, 4095u);
    ((uint4*)h)[t] = o;
}

// ---------------- bins -> split-bf16 weights + row sums ----------------
__device__ __forceinline__ float wcalc(unsigned bin, const unsigned* __restrict__ lut) {
    unsigned p = __ldg(&lut[bin]);
    float SA  = (float)(p >> 12);
    float cnt = (float)(p & 4095u);
    float rank = SA + 0.5f * (cnt - 1.0f);
    return -__logf((rank + 1.0f) * INV_N);
}
__global__ __launch_bounds__(256) void k_weight() {
    int row  = blockIdx.x;
    int head = row >> 10;
    int t    = threadIdx.x;
    const unsigned* lut = g_hist + (size_t)head * NB;
    uint4 b = ((const uint4*)(g_bins + (size_t)row * SEQ))[t];
    float w0 = wcalc(b.x, lut), w1 = wcalc(b.y, lut);
    float w2 = wcalc(b.z, lut), w3 = wcalc(b.w, lut);

    __nv_bfloat16 h0,l0,h1,l1,h2,l2,h3,l3;
    split2(w0,h0,l0); split2(w1,h1,l1); split2(w2,h2,l2); split2(w3,h3,l3);
    size_t o = (size_t)row * SEQ + t*4;
    ((__nv_bfloat162*)(g_whi + o))[0] = __halves2bfloat162(h0,h1);
    ((__nv_bfloat162*)(g_whi + o))[1] = __halves2bfloat162(h2,h3);
    ((__nv_bfloat162*)(g_wlo + o))[0] = __halves2bfloat162(l0,l1);
    ((__nv_bfloat162*)(g_wlo + o))[1] = __halves2bfloat162(l2,l3);

    float sum = w0 + w1 + w2 + w3;
    __shared__ float sm[8];
    #pragma unroll
    for (int o2 = 16; o2; o2 >>= 1) sum += __shfl_xor_sync(0xffffffffu, sum, o2);
    if ((t & 31) == 0) sm[t >> 5] = sum;
    __syncthreads();
    if (t < 8) {
        float v = sm[t];
        #pragma unroll
        for (int o2 = 4; o2; o2 >>= 1) v += __shfl_xor_sync(0xffu, v, o2);
        if (t == 0) g_rowsum[row] = v;
    }
}

// ---------------- output GEMM (HMMA, split bf16): O = (W @ V) / rowsum ------
__global__ __launch_bounds__(256) void k_out(float* __restrict__ O) {
    extern __shared__ __nv_bfloat16 sm[];
    const int WH = 0, WL = 128*STRD, VH = 2*128*STRD, VL = 2*128*STRD + 64*STRD;
    int tid = threadIdx.x, wid = tid >> 5, lane = tid & 31;
    int qt = blockIdx.x, head = blockIdx.y;

    size_t wbase = (size_t)head*SEQ + qt*128;       // row offset into W
    size_t vbase = (size_t)head*64;                 // row offset into V^T

    unsigned sb = s2u(sm);
    unsigned arow = wid*16 + (lane & 15);
    unsigned acol = (lane >> 4) * 8;
    unsigned aH = sb + (WH + arow*STRD + acol) * 2;
    unsigned aL = sb + (WL + arow*STRD + acol) * 2;
    unsigned brow = (lane & 7) + ((lane >> 4) << 3);
    unsigned bcol = ((lane >> 3) & 1) * 8;
    unsigned bHa = sb + (VH + brow*STRD + bcol) * 2;
    unsigned bLa = sb + (VL + brow*STRD + bcol) * 2;

    float acc[8][4];
    #pragma unroll
    for (int i = 0; i < 8; i++) { acc[i][0]=0; acc[i][1]=0; acc[i][2]=0; acc[i][3]=0; }

    for (int ch = 0; ch < 16; ch++) {
        // load W tiles (128 x 64) hi+lo
        #pragma unroll
        for (int j = 0; j < 4; j++) {
            int idx = tid + j*256;
            int r = idx >> 3, c = idx & 7;
            *(uint4*)&sm[WH + r*STRD + c*8] =
                *(const uint4*)(g_whi + (wbase + r)*SEQ + ch*64 + c*8);
            *(uint4*)&sm[WL + r*STRD + c*8] =
                *(const uint4*)(g_wlo + (wbase + r)*SEQ + ch*64 + c*8);
        }
        // load V^T tiles (64 x 64) hi+lo
        #pragma unroll
        for (int j = 0; j < 2; j++) {
            int idx = tid + j*256;
            int r = idx >> 3, c = idx & 7;
            *(uint4*)&sm[VH + r*STRD + c*8] =
                *(const uint4*)(g_vthi + (vbase + r)*SEQ + ch*64 + c*8);
            *(uint4*)&sm[VL + r*STRD + c*8] =
                *(const uint4*)(g_vtlo + (vbase + r)*SEQ + ch*64 + c*8);
        }
        __syncthreads();

        unsigned ah[4][4], al[4][4];
        #pragma unroll
        for (int ks = 0; ks < 4; ks++) { ldm4(ah[ks], aH + ks*32); ldm4(al[ks], aL + ks*32); }

        #pragma unroll
        for (int np = 0; np < 4; np++) {
            #pragma unroll
            for (int ks = 0; ks < 4; ks++) {
                unsigned bh[4], bl[4];
                ldm4(bh, bHa + np*16*STRD*2 + ks*32);
                ldm4(bl, bLa + np*16*STRD*2 + ks*32);
                mma16816(acc[2*np],   ah[ks], bh[0], bh[1]);
                mma16816(acc[2*np+1], ah[ks], bh[2], bh[3]);
                mma16816(acc[2*np],   ah[ks], bl[0], bl[1]);
                mma16816(acc[2*np+1], ah[ks], bl[2], bl[3]);
                mma16816(acc[2*np],   al[ks], bh[0], bh[1]);
                mma16816(acc[2*np+1], al[ks], bh[2], bh[3]);
            }
        }
        __syncthreads();
    }

    int r0 = wid*16 + (lane >> 2);
    int cb = (lane & 3) * 2;
    float inv0 = 1.0f / g_rowsum[head*SEQ + qt*128 + r0];
    float inv1 = 1.0f / g_rowsum[head*SEQ + qt*128 + r0 + 8];
    float* op0 = O + ((size_t)head*SEQ + qt*128 + r0) * 64;
    float* op1 = op0 + 8*64;
    #pragma unroll
    for (int nt = 0; nt < 8; nt++) {
        int c = nt*8 + cb;
        *(float2*)&op0[c] = make_float2(acc[nt][0]*inv0, acc[nt][1]*inv0);
        *(float2*)&op1[c] = make_float2(acc[nt][2]*inv1, acc[nt][3]*inv1);
    }
}

// ---------------- launch ----------------
extern "C" void kernel_launch(void* const* d_in, const int* in_sizes, int n_in,
                              void* d_out, int out_size) {
    const float* q = (const float*)d_in[0];
    const float* k = (const float*)d_in[1];
    const float* v = (const float*)d_in[2];
    float* o = (float*)d_out;

    static int inited = 0;
    if (!inited) {
        cudaFuncSetAttribute(k_score, cudaFuncAttributeMaxDynamicSharedMemorySize, 4*128*STRD*2);
        cudaFuncSetAttribute(k_out,   cudaFuncAttributeMaxDynamicSharedMemorySize, (2*128+2*64)*STRD*2);
        inited = 1;
    }

    k_clear  <<<8192, 256>>>();
    k_qksplit<<<16384, 256>>>(q, k);
    k_vsplit <<<dim3(16,64), 256>>>(v);
    k_score  <<<dim3(8,8,64), 256, 4*128*STRD*2>>>();
    k_hpart  <<<dim3(128,64), 256>>>();
    k_hscan  <<<64, 128>>>();
    k_hfinal <<<dim3(128,64), 256>>>();
    k_weight <<<65536, 256>>>();
    k_out    <<<dim3(8,64), 256, (2*128+2*64)*STRD*2>>>(o);
}